// round 2
// baseline (speedup 1.0000x reference)
#include <cuda_runtime.h>
#include <math.h>

#define B_    8
#define D_    512
#define L_    1024
#define NPOS  8192          // B_*L_
#define KCB   8192          // number of codes
#define EDIM  512
#define SEMD  256
#define NQ    4194304       // B_*D_*L_  (z_q element count)

typedef unsigned long long ull;

// ---------------- scratch (static device globals; no allocation) ----------------
static __device__ float g_Zn[NPOS * EDIM];     // normalized queries, (n, e) row-major
static __device__ float g_En[KCB * EDIM];      // normalized codes,   (k, e) row-major
static __device__ float g_psum[8][NPOS];       // partial sumsq of z per 64-d segment
static __device__ float g_invk[NPOS], g_invg[NPOS];
static __device__ float g_akd[NPOS],  g_agan[NPOS];
static __device__ float g_bkd[KCB],   g_bgan[KCB];
static __device__ float g_pSkd[2][NPOS], g_pSgan[2][NPOS], g_pBv[2][NPOS];
static __device__ int   g_pBi[2][NPOS];
static __device__ int   g_idx[NPOS];

// ---------------- small helpers ----------------
__device__ __forceinline__ ull ffma2(ull a, ull b, ull c) {
    ull d;
    asm("fma.rn.f32x2 %0, %1, %2, %3;" : "=l"(d) : "l"(a), "l"(b), "l"(c));
    return d;
}
__device__ __forceinline__ void upk(ull v, float &lo, float &hi) {
    asm("mov.b64 {%0, %1}, %2;" : "=f"(lo), "=f"(hi) : "l"(v));
}
__device__ __forceinline__ float wsum(float s) {
#pragma unroll
    for (int o = 16; o > 0; o >>= 1) s += __shfl_xor_sync(0xffffffffu, s, o);
    return s;
}

// ---------------- 1. normalize embeddings (one warp per code row) ----------------
__global__ void k_emb(const float* __restrict__ ekd, const float* __restrict__ egan) {
    int w    = threadIdx.x >> 5;
    int lane = threadIdx.x & 31;
    int k    = blockIdx.x * 8 + w;
    if (k >= KCB) return;

    // kd half
    {
        const float* p = ekd + (size_t)k * SEMD;
        float v[8]; float s = 0.f;
#pragma unroll
        for (int j = 0; j < 8; ++j) { v[j] = p[lane + j * 32]; s += v[j] * v[j]; }
        s = wsum(s);
        float inv = 1.f / fmaxf(sqrtf(s), 1e-12f);
        float t = 0.f;
#pragma unroll
        for (int j = 0; j < 8; ++j) {
            float nv = v[j] * inv;
            g_En[(size_t)k * EDIM + lane + j * 32] = nv;
            t += nv * nv;
        }
        t = wsum(t);
        if (lane == 0) g_bkd[k] = t;
    }
    // gan half
    {
        const float* p = egan + (size_t)k * SEMD;
        float v[8]; float s = 0.f;
#pragma unroll
        for (int j = 0; j < 8; ++j) { v[j] = p[lane + j * 32]; s += v[j] * v[j]; }
        s = wsum(s);
        float inv = 1.f / fmaxf(sqrtf(s), 1e-12f);
        float t = 0.f;
#pragma unroll
        for (int j = 0; j < 8; ++j) {
            float nv = v[j] * inv;
            g_En[(size_t)k * EDIM + SEMD + lane + j * 32] = nv;
            t += nv * nv;
        }
        t = wsum(t);
        if (lane == 0) g_bgan[k] = t;
    }
}

// ---------------- 2. z sum-of-squares partials (coalesced over l) ----------------
__global__ void k_zsumsq(const float* __restrict__ z) {
    int l   = blockIdx.x * 256 + threadIdx.x;   // grid.x = 4
    int b   = blockIdx.y;                       // grid.y = 8
    int seg = blockIdx.z;                       // grid.z = 8 (64 d each)
    const float* p = z + (size_t)b * D_ * L_ + (size_t)seg * 64 * L_ + l;
    float s = 0.f;
#pragma unroll 8
    for (int d = 0; d < 64; ++d) { float v = p[(size_t)d * L_]; s += v * v; }
    g_psum[seg][b * L_ + l] = s;
}

// ---------------- 3. finalize norms ----------------
__global__ void k_zfinal() {
    int n = blockIdx.x * 256 + threadIdx.x;
    float s = g_psum[0][n]; s += g_psum[1][n]; s += g_psum[2][n]; s += g_psum[3][n];
    float inv = 1.f / fmaxf(sqrtf(s), 1e-12f);
    g_invk[n] = inv;
    g_akd[n]  = s * inv * inv;
    float s2 = g_psum[4][n]; s2 += g_psum[5][n]; s2 += g_psum[6][n]; s2 += g_psum[7][n];
    float inv2 = 1.f / fmaxf(sqrtf(s2), 1e-12f);
    g_invg[n] = inv2;
    g_agan[n] = s2 * inv2 * inv2;
}

// ---------------- 4. transpose + normalize z into Zn (n, e) ----------------
__global__ void k_ztrans(const float* __restrict__ z) {
    __shared__ float s[32][33];
    int d0 = blockIdx.x * 32;   // grid.x = 16
    int l0 = blockIdx.y * 32;   // grid.y = 32
    int b  = blockIdx.z;        // grid.z = 8
    int tx = threadIdx.x;       // 32
    int ty2 = threadIdx.y;      // 8
#pragma unroll
    for (int q = 0; q < 4; ++q) {
        int dy = ty2 * 4 + q;
        s[dy][tx] = z[((size_t)b * D_ + d0 + dy) * L_ + l0 + tx];
    }
    __syncthreads();
    bool kdh = (d0 < SEMD);
#pragma unroll
    for (int q = 0; q < 4; ++q) {
        int lr = ty2 * 4 + q;
        int n  = b * L_ + l0 + lr;
        float inv = kdh ? g_invk[n] : g_invg[n];
        g_Zn[(size_t)n * EDIM + d0 + tx] = s[tx][lr] * inv;
    }
}

// ---------------- 5. fused GEMM + distance stats + argmin (split-K=2) ----------------
__global__ void __launch_bounds__(256, 2) k_gemm() {
    const int rt    = blockIdx.x;     // 0..127 row tile
    const int split = blockIdx.y;     // 0..1
    const int row0  = rt * 64;
    const int kbase = split * 4096;
    const int tid = threadIdx.x;
    const int tx = tid & 15, ty = tid >> 4;
    const int ty4 = ty * 4;
    const int lr = tid >> 2;                 // loader row 0..63
    const int lc = (tid & 3) * 8;            // loader col base {0,8,16,24}

    union Sm {
        struct { float2 A[64][33]; float B[32][66]; } t;   // A duplicated pairs
        struct { float S1[64][17]; float S2[64][17]; float Bv[64][17]; int Bi[64][17]; } r;
    };
    __shared__ Sm sm;

    ull acck[4][2], accg[4][2];
#pragma unroll
    for (int i = 0; i < 4; ++i) { acck[i][0] = 0ull; acck[i][1] = 0ull; accg[i][0] = 0ull; accg[i][1] = 0ull; }

    float Skd[4]  = {0.f, 0.f, 0.f, 0.f};
    float Sgan[4] = {0.f, 0.f, 0.f, 0.f};
    float bestv[4]; int besti[4];
    float ak[4], ag[4];
#pragma unroll
    for (int i = 0; i < 4; ++i) {
        ak[i] = g_akd[row0 + ty4 + i];
        ag[i] = g_agan[row0 + ty4 + i];
        bestv[i] = 3.402823466e38f; besti[i] = 0;
    }

    const float* Abase = g_Zn + (size_t)(row0 + lr) * EDIM + lc;

    float4 pa0, pa1, pb0, pb1;
    auto prefetch = [&](int it) {
        int kt = it >> 4;
        int db = ((it >> 3) & 1) * 256 + (it & 7) * 32;
        const float* Ap = Abase + db;
        const float* Bp = g_En + (size_t)(kbase + kt * 64 + lr) * EDIM + lc + db;
        pa0 = *(const float4*)(Ap);
        pa1 = *(const float4*)(Ap + 4);
        pb0 = *(const float4*)(Bp);
        pb1 = *(const float4*)(Bp + 4);
    };

    auto compute_phase = [&](ull (&acc)[4][2]) {
#pragma unroll
        for (int dd = 0; dd < 32; ++dd) {
            ull A0 = *(const ull*)&sm.t.A[ty4 + 0][dd];
            ull A1 = *(const ull*)&sm.t.A[ty4 + 1][dd];
            ull A2 = *(const ull*)&sm.t.A[ty4 + 2][dd];
            ull A3 = *(const ull*)&sm.t.A[ty4 + 3][dd];
            ull B0 = *(const ull*)&sm.t.B[dd][tx * 4];
            ull B1 = *(const ull*)&sm.t.B[dd][tx * 4 + 2];
            acc[0][0] = ffma2(A0, B0, acc[0][0]); acc[0][1] = ffma2(A0, B1, acc[0][1]);
            acc[1][0] = ffma2(A1, B0, acc[1][0]); acc[1][1] = ffma2(A1, B1, acc[1][1]);
            acc[2][0] = ffma2(A2, B0, acc[2][0]); acc[2][1] = ffma2(A2, B1, acc[2][1]);
            acc[3][0] = ffma2(A3, B0, acc[3][0]); acc[3][1] = ffma2(A3, B1, acc[3][1]);
        }
    };

    prefetch(0);
    for (int it = 0; it < 1024; ++it) {            // 64 k-tiles * 2 phases * 8 d-chunks
        __syncthreads();
        // stage A (duplicated) and B (dd-major)
        sm.t.A[lr][lc + 0] = make_float2(pa0.x, pa0.x);
        sm.t.A[lr][lc + 1] = make_float2(pa0.y, pa0.y);
        sm.t.A[lr][lc + 2] = make_float2(pa0.z, pa0.z);
        sm.t.A[lr][lc + 3] = make_float2(pa0.w, pa0.w);
        sm.t.A[lr][lc + 4] = make_float2(pa1.x, pa1.x);
        sm.t.A[lr][lc + 5] = make_float2(pa1.y, pa1.y);
        sm.t.A[lr][lc + 6] = make_float2(pa1.z, pa1.z);
        sm.t.A[lr][lc + 7] = make_float2(pa1.w, pa1.w);
        sm.t.B[lc + 0][lr] = pb0.x;
        sm.t.B[lc + 1][lr] = pb0.y;
        sm.t.B[lc + 2][lr] = pb0.z;
        sm.t.B[lc + 3][lr] = pb0.w;
        sm.t.B[lc + 4][lr] = pb1.x;
        sm.t.B[lc + 5][lr] = pb1.y;
        sm.t.B[lc + 6][lr] = pb1.z;
        sm.t.B[lc + 7][lr] = pb1.w;
        __syncthreads();
        if (it != 1023) prefetch(it + 1);

        if (((it >> 3) & 1) == 0) compute_phase(acck);
        else                      compute_phase(accg);

        if ((it & 15) == 15) {
            int k0 = kbase + (it >> 4) * 64;
#pragma unroll
            for (int p = 0; p < 2; ++p) {
                int kA = k0 + tx * 4 + p * 2;
                float bkA = g_bkd[kA],     bgA = g_bgan[kA];
                float bkB = g_bkd[kA + 1], bgB = g_bgan[kA + 1];
#pragma unroll
                for (int i = 0; i < 4; ++i) {
                    float cklo, ckhi, cglo, cghi;
                    upk(acck[i][p], cklo, ckhi);
                    upk(accg[i][p], cglo, cghi);
                    // (a+b) - 2c : matches reference rounding (2c is exact)
                    float dkA = (ak[i] + bkA) - 2.f * cklo;
                    float dgA = (ag[i] + bgA) - 2.f * cglo;
                    Skd[i]  = fmaf(dkA, dkA, Skd[i]);
                    Sgan[i] = fmaf(dgA, dgA, Sgan[i]);
                    float dA = dkA + dgA;
                    if (dA < bestv[i]) { bestv[i] = dA; besti[i] = kA; }
                    float dkB = (ak[i] + bkB) - 2.f * ckhi;
                    float dgB = (ag[i] + bgB) - 2.f * cghi;
                    Skd[i]  = fmaf(dkB, dkB, Skd[i]);
                    Sgan[i] = fmaf(dgB, dgB, Sgan[i]);
                    float dB = dkB + dgB;
                    if (dB < bestv[i]) { bestv[i] = dB; besti[i] = kA + 1; }
                    acck[i][p] = 0ull; accg[i][p] = 0ull;
                }
            }
        }
    }

    // CTA reduction across tx (16 partials per row)
    __syncthreads();
#pragma unroll
    for (int i = 0; i < 4; ++i) {
        sm.r.S1[ty4 + i][tx] = Skd[i];
        sm.r.S2[ty4 + i][tx] = Sgan[i];
        sm.r.Bv[ty4 + i][tx] = bestv[i];
        sm.r.Bi[ty4 + i][tx] = besti[i];
    }
    __syncthreads();
    if (tid < 64) {
        float s1 = 0.f, s2 = 0.f, bv = 3.402823466e38f; int bi = 0;
#pragma unroll
        for (int e = 0; e < 16; ++e) {
            s1 += sm.r.S1[tid][e];
            s2 += sm.r.S2[tid][e];
            float v = sm.r.Bv[tid][e]; int ii = sm.r.Bi[tid][e];
            if (v < bv || (v == bv && ii < bi)) { bv = v; bi = ii; }
        }
        int n = row0 + tid;
        g_pSkd[split][n] = s1;
        g_pSgan[split][n] = s2;
        g_pBv[split][n] = bv;
        g_pBi[split][n] = bi;
    }
}

// ---------------- 6. combine splits, emit idx ----------------
__global__ void k_combine(float* __restrict__ out) {
    int n = blockIdx.x * 256 + threadIdx.x;
    float v0 = g_pBv[0][n], v1 = g_pBv[1][n];
    int idx = (v1 < v0) ? g_pBi[1][n] : g_pBi[0][n];   // tie -> split 0 (smaller k)
    g_idx[n] = idx;
    out[NQ + 2 + n] = (float)idx;
}

// ---------------- 7. scalar reductions ----------------
__global__ void k_scalar(float* __restrict__ out) {
    __shared__ float r1[256], r2[256];
    int t = threadIdx.x;
    float s1 = 0.f, s2 = 0.f;
    for (int m = 0; m < 32; ++m) {
        int n = t + m * 256;
        s1 += g_pSkd[0][n] + g_pSkd[1][n];
        s2 += g_pSgan[0][n] + g_pSgan[1][n];
    }
    r1[t] = s1; r2[t] = s2;
    __syncthreads();
    for (int s = 128; s > 0; s >>= 1) {
        if (t < s) { r1[t] += r1[t + s]; r2[t] += r2[t + s]; }
        __syncthreads();
    }
    if (t == 0) {
        out[NQ]     = r1[0] * (1.f / 8192.f);
        out[NQ + 1] = r2[0] * (1.f / 8192.f);
    }
}

// ---------------- 8. z_q gather (STE rounding replicated exactly) ----------------
__global__ void k_zq(float* __restrict__ out) {
    int row0 = blockIdx.x * 64;          // 128 blocks
    int b  = row0 >> 10;
    int l0 = row0 & 1023;
    int lq = threadIdx.x & 63;
    int dg = threadIdx.x >> 6;           // 0..3
    int n  = row0 + lq;
    int kidx = g_idx[n];
    const float* Erow = g_En + (size_t)kidx * EDIM;
    const float* Zrow = g_Zn + (size_t)n * EDIM;
#pragma unroll 4
    for (int dit = 0; dit < 128; ++dit) {
        int d = dg * 128 + dit;
        float ev = Erow[d];
        float zn = Zrow[d];
        out[((size_t)b * D_ + d) * L_ + l0 + lq] = zn + (ev - zn);
    }
}

// ---------------- launch ----------------
extern "C" void kernel_launch(void* const* d_in, const int* in_sizes, int n_in,
                              void* d_out, int out_size) {
    (void)in_sizes; (void)n_in; (void)out_size;
    const float* z    = (const float*)d_in[0];
    const float* ekd  = (const float*)d_in[1];
    const float* egan = (const float*)d_in[2];
    float* out = (float*)d_out;

    k_emb<<<KCB / 8, 256>>>(ekd, egan);
    k_zsumsq<<<dim3(4, 8, 8), 256>>>(z);
    k_zfinal<<<NPOS / 256, 256>>>();
    k_ztrans<<<dim3(16, 32, 8), dim3(32, 8)>>>(z);
    k_gemm<<<dim3(128, 2), 256>>>();
    k_combine<<<NPOS / 256, 256>>>(out);
    k_scalar<<<1, 256>>>(out);
    k_zq<<<128, 256>>>(out);
}

// round 3
// speedup vs baseline: 2.5531x; 2.5531x over previous
#include <cuda_runtime.h>
#include <math.h>

#define B_    8
#define D_    512
#define L_    1024
#define NPOS  8192
#define KCB   8192
#define EDIM  512
#define SEMD  256
#define NQ    4194304
#define UNITS 8192
#define GG    296

typedef unsigned long long ull;

static __device__ float g_ZnT[EDIM * NPOS];   // (e, n)
static __device__ float g_EnT[EDIM * KCB];    // (e, k)
static __device__ float g_psum[8][NPOS];
static __device__ float g_invk[NPOS], g_invg[NPOS];
static __device__ float g_akd[NPOS],  g_agan[NPOS];
static __device__ float g_bkd[KCB],   g_bgan[KCB];
static __device__ ull   g_key[NPOS];
static __device__ float g_S[2];
static __device__ int   g_idx[NPOS];

__device__ __forceinline__ ull ffma2(ull a, ull b, ull c) {
    ull d; asm("fma.rn.f32x2 %0, %1, %2, %3;" : "=l"(d) : "l"(a), "l"(b), "l"(c)); return d;
}
__device__ __forceinline__ void upk(ull v, float &lo, float &hi) {
    asm("mov.b64 {%0, %1}, %2;" : "=f"(lo), "=f"(hi) : "l"(v));
}
__device__ __forceinline__ ull dup2(float x) {
    ull r; asm("mov.b64 %0, {%1, %1};" : "=l"(r) : "f"(x)); return r;
}
__device__ __forceinline__ float wsum(float s) {
#pragma unroll
    for (int o = 16; o > 0; o >>= 1) s += __shfl_xor_sync(0xffffffffu, s, o);
    return s;
}
__device__ __forceinline__ void cpasync16(unsigned s, const void* g) {
    asm volatile("cp.async.cg.shared.global [%0], [%1], 16;\n" :: "r"(s), "l"(g));
}

// 1. normalize embeddings -> EnT (e,k) + b-norms
__global__ void k_emb(const float* __restrict__ ekd, const float* __restrict__ egan) {
    __shared__ float sm[EDIM * 12];
    int w = threadIdx.x >> 5, lane = threadIdx.x & 31;
    int k = blockIdx.x * 8 + w;
#pragma unroll
    for (int h = 0; h < 2; ++h) {
        const float* p = (h ? egan : ekd) + (size_t)k * SEMD;
        float v[8]; float s = 0.f;
#pragma unroll
        for (int j = 0; j < 8; ++j) { v[j] = p[lane + j * 32]; s += v[j] * v[j]; }
        s = wsum(s);
        float inv = 1.f / fmaxf(sqrtf(s), 1e-12f);
        float t = 0.f;
#pragma unroll
        for (int j = 0; j < 8; ++j) {
            float nv = v[j] * inv;
            sm[(h * SEMD + lane + j * 32) * 12 + w] = nv;
            t += nv * nv;
        }
        t = wsum(t);
        if (lane == 0) { if (h) g_bgan[k] = t; else g_bkd[k] = t; }
    }
    __syncthreads();
    int t = threadIdx.x, k0 = blockIdx.x * 8;
#pragma unroll
    for (int rr = 0; rr < 2; ++rr) {
        int e = t * 2 + rr;
        *(float4*)(g_EnT + (size_t)e * KCB + k0)     = *(const float4*)&sm[e * 12];
        *(float4*)(g_EnT + (size_t)e * KCB + k0 + 4) = *(const float4*)&sm[e * 12 + 4];
    }
}

// 2. z sumsq partials
__global__ void k_zsumsq(const float* __restrict__ z) {
    int l = blockIdx.x * 256 + threadIdx.x, b = blockIdx.y, seg = blockIdx.z;
    const float* p = z + (size_t)b * D_ * L_ + (size_t)seg * 64 * L_ + l;
    float s = 0.f;
#pragma unroll 8
    for (int d = 0; d < 64; ++d) { float v = p[(size_t)d * L_]; s += v * v; }
    g_psum[seg][b * L_ + l] = s;
}

// 3. finalize norms + init key/S
__global__ void k_zfinal() {
    int n = blockIdx.x * 256 + threadIdx.x;
    float s = g_psum[0][n] + g_psum[1][n] + g_psum[2][n] + g_psum[3][n];
    float inv = 1.f / fmaxf(sqrtf(s), 1e-12f);
    g_invk[n] = inv; g_akd[n] = s * inv * inv;
    float s2 = g_psum[4][n] + g_psum[5][n] + g_psum[6][n] + g_psum[7][n];
    float inv2 = 1.f / fmaxf(sqrtf(s2), 1e-12f);
    g_invg[n] = inv2; g_agan[n] = s2 * inv2 * inv2;
    g_key[n] = ~0ull;
    if (n < 2) g_S[n] = 0.f;
}

// 4. normalized z in (e, n) layout (z already d-major -> coalesced copy)
__global__ void k_znormT(const float* __restrict__ z) {
    int d = blockIdx.x, b = blockIdx.y, l4 = threadIdx.x * 4;
    int n = b * L_ + l4;
    float4 v = *(const float4*)(z + ((size_t)b * D_ + d) * L_ + l4);
    float4 iv = *(const float4*)(((d < SEMD) ? g_invk : g_invg) + n);
    float4 o = make_float4(v.x * iv.x, v.y * iv.y, v.z * iv.z, v.w * iv.w);
    *(float4*)(g_ZnT + (size_t)d * NPOS + n) = o;
}

// 5. persistent fused GEMM + argmin + d-norm sums
__global__ void __launch_bounds__(256, 2) k_gemm() {
    __shared__ float sA[2][32 * 128];
    __shared__ float sB[2][32 * 64];

    const int t = threadIdx.x;
    const int tx = t & 15, ty = t >> 4;

    int aSrc[4], aDst[4], bSrc[2], bDst[2];
#pragma unroll
    for (int r = 0; r < 4; ++r) {
        int q = t + r * 256;
        aSrc[r] = (q >> 5) * NPOS + (q & 31) * 4;
        aDst[r] = ((q >> 5) * 128 + (q & 31) * 4) * 4;
    }
#pragma unroll
    for (int r = 0; r < 2; ++r) {
        int q = t + r * 256;
        bSrc[r] = (q >> 4) * KCB + (q & 15) * 4;
        bDst[r] = ((q >> 4) * 64 + (q & 15) * 4) * 4;
    }
    unsigned sAb = (unsigned)__cvta_generic_to_shared(&sA[0][0]);
    unsigned sBb = (unsigned)__cvta_generic_to_shared(&sB[0][0]);

    auto load_chunk = [&](int uu, int cc, int bf) {
        const float* As = g_ZnT + (size_t)(cc * 32) * NPOS + (uu >> 7) * 128;
        const float* Bs = g_EnT + (size_t)(cc * 32) * KCB + (uu & 127) * 64;
        unsigned ab = sAb + bf * (32 * 128 * 4);
        unsigned bb = sBb + bf * (32 * 64 * 4);
#pragma unroll
        for (int r = 0; r < 4; ++r) cpasync16(ab + aDst[r], As + aSrc[r]);
#pragma unroll
        for (int r = 0; r < 2; ++r) cpasync16(bb + bDst[r], Bs + bSrc[r]);
        asm volatile("cp.async.commit_group;\n" ::: "memory");
    };

    ull acck[4][4], accg[4][4];
#pragma unroll
    for (int i = 0; i < 4; ++i)
#pragma unroll
        for (int j = 0; j < 4; ++j) { acck[i][j] = 0ull; accg[i][j] = 0ull; }
    float Sk = 0.f, Sg = 0.f;

    auto compute = [&](int bf, ull (&acc)[4][4]) {
        const float* pAb = &sA[bf][ty * 8];
        const float* pBb = &sB[bf][tx * 4];
#pragma unroll 8
        for (int dd = 0; dd < 32; ++dd) {
            ulonglong2 a01 = *(const ulonglong2*)(pAb + dd * 128);
            ulonglong2 a23 = *(const ulonglong2*)(pAb + dd * 128 + 4);
            float4 bv = *(const float4*)(pBb + dd * 64);
            ull B0 = dup2(bv.x), B1 = dup2(bv.y), B2 = dup2(bv.z), B3 = dup2(bv.w);
            acc[0][0] = ffma2(a01.x, B0, acc[0][0]);
            acc[0][1] = ffma2(a01.x, B1, acc[0][1]);
            acc[0][2] = ffma2(a01.x, B2, acc[0][2]);
            acc[0][3] = ffma2(a01.x, B3, acc[0][3]);
            acc[1][0] = ffma2(a01.y, B0, acc[1][0]);
            acc[1][1] = ffma2(a01.y, B1, acc[1][1]);
            acc[1][2] = ffma2(a01.y, B2, acc[1][2]);
            acc[1][3] = ffma2(a01.y, B3, acc[1][3]);
            acc[2][0] = ffma2(a23.x, B0, acc[2][0]);
            acc[2][1] = ffma2(a23.x, B1, acc[2][1]);
            acc[2][2] = ffma2(a23.x, B2, acc[2][2]);
            acc[2][3] = ffma2(a23.x, B3, acc[2][3]);
            acc[3][0] = ffma2(a23.y, B0, acc[3][0]);
            acc[3][1] = ffma2(a23.y, B1, acc[3][1]);
            acc[3][2] = ffma2(a23.y, B2, acc[3][2]);
            acc[3][3] = ffma2(a23.y, B3, acc[3][3]);
        }
    };

    int u = blockIdx.x;
    if (u < UNITS) load_chunk(u, 0, 0);
    int buf = 0;

    while (u < UNITS) {
        const int rt = u >> 7, kt = u & 127;
#pragma unroll 1
        for (int c = 0; c < 16; ++c) {
            asm volatile("cp.async.wait_group 0;\n" ::: "memory");
            __syncthreads();
            int nu = u, nc = c + 1;
            if (c == 15) { nu = u + GG; nc = 0; }
            if (nu < UNITS) load_chunk(nu, nc, buf ^ 1);
            if (c < 8) compute(buf, acck);
            else       compute(buf, accg);
            buf ^= 1;
        }
        // epilogue
        int kb = kt * 64 + tx * 4;
        float bk[4], bg[4];
#pragma unroll
        for (int j = 0; j < 4; ++j) { bk[j] = g_bkd[kb + j]; bg[j] = g_bgan[kb + j]; }
        int n0 = rt * 128 + ty * 8;
#pragma unroll
        for (int i = 0; i < 4; ++i) {
            float akl = g_akd[n0 + 2 * i],  akh = g_akd[n0 + 2 * i + 1];
            float agl = g_agan[n0 + 2 * i], agh = g_agan[n0 + 2 * i + 1];
            ull keyl = ~0ull, keyh = ~0ull;
#pragma unroll
            for (int j = 0; j < 4; ++j) {
                float ckl, ckh, cgl, cgh;
                upk(acck[i][j], ckl, ckh);
                upk(accg[i][j], cgl, cgh);
                float dkl = (akl + bk[j]) - 2.f * ckl;
                float dgl = (agl + bg[j]) - 2.f * cgl;
                Sk = fmaf(dkl, dkl, Sk); Sg = fmaf(dgl, dgl, Sg);
                float dl = dkl + dgl;
                ull kl = ((ull)__float_as_uint(dl) << 32) | (unsigned)(kb + j);
                keyl = min(keyl, kl);
                float dkh = (akh + bk[j]) - 2.f * ckh;
                float dgh = (agh + bg[j]) - 2.f * cgh;
                Sk = fmaf(dkh, dkh, Sk); Sg = fmaf(dgh, dgh, Sg);
                float dh = dkh + dgh;
                ull kh = ((ull)__float_as_uint(dh) << 32) | (unsigned)(kb + j);
                keyh = min(keyh, kh);
                acck[i][j] = 0ull; accg[i][j] = 0ull;
            }
#pragma unroll
            for (int o = 8; o > 0; o >>= 1) {
                keyl = min(keyl, __shfl_xor_sync(0xffffffffu, keyl, o));
                keyh = min(keyh, __shfl_xor_sync(0xffffffffu, keyh, o));
            }
            if (tx == 0) {
                atomicMin(&g_key[n0 + 2 * i], keyl);
                atomicMin(&g_key[n0 + 2 * i + 1], keyh);
            }
        }
        u += GG;
    }
    // global S reduction
    Sk = wsum(Sk); Sg = wsum(Sg);
    if ((t & 31) == 0) { atomicAdd(&g_S[0], Sk); atomicAdd(&g_S[1], Sg); }
}

// 6. idx + scalars
__global__ void k_post(float* __restrict__ out) {
    int n = blockIdx.x * 256 + threadIdx.x;
    int idx = (int)(unsigned)g_key[n];
    g_idx[n] = idx;
    out[NQ + 2 + n] = (float)idx;
    if (n == 0) out[NQ]     = g_S[0] * (1.f / 8192.f);
    if (n == 1) out[NQ + 1] = g_S[1] * (1.f / 8192.f);
}

// 7. z_q gather (STE rounding replicated)
__global__ void k_zq(float* __restrict__ out) {
    int d = blockIdx.x, b = blockIdx.y, l4 = threadIdx.x * 4;
    int n = b * L_ + l4;
    float4 zn = *(const float4*)(g_ZnT + (size_t)d * NPOS + n);
    int4 id = *(const int4*)(g_idx + n);
    const float* Ed = g_EnT + (size_t)d * KCB;
    float4 o;
    o.x = zn.x + (Ed[id.x] - zn.x);
    o.y = zn.y + (Ed[id.y] - zn.y);
    o.z = zn.z + (Ed[id.z] - zn.z);
    o.w = zn.w + (Ed[id.w] - zn.w);
    *(float4*)(out + ((size_t)b * D_ + d) * L_ + l4) = o;
}

extern "C" void kernel_launch(void* const* d_in, const int* in_sizes, int n_in,
                              void* d_out, int out_size) {
    (void)in_sizes; (void)n_in; (void)out_size;
    const float* z    = (const float*)d_in[0];
    const float* ekd  = (const float*)d_in[1];
    const float* egan = (const float*)d_in[2];
    float* out = (float*)d_out;

    k_emb<<<KCB / 8, 256>>>(ekd, egan);
    k_zsumsq<<<dim3(4, 8, 8), 256>>>(z);
    k_zfinal<<<NPOS / 256, 256>>>();
    k_znormT<<<dim3(512, 8), 256>>>(z);
    k_gemm<<<GG, 256>>>();
    k_post<<<NPOS / 256, 256>>>(out);
    k_zq<<<dim3(512, 8), 256>>>(out);
}

// round 5
// speedup vs baseline: 6.5064x; 2.5484x over previous
#include <cuda_runtime.h>
#include <cuda_bf16.h>
#include <math.h>
#include <stdint.h>

#define B_    8
#define D_    512
#define L_    1024
#define NPOS  8192
#define KCB   8192
#define EDIM  512
#define SEMD  256
#define NQ    4194304

typedef unsigned long long ull;

// ---------------- scratch ----------------
static __device__ float          g_Zn [NPOS * EDIM];   // exact normalized queries (n, e)
static __device__ __nv_bfloat16  g_ZnB[NPOS * EDIM];   // bf16 copy
static __device__ float          g_En [KCB * EDIM];    // exact normalized codes (k, e)
static __device__ __nv_bfloat16  g_EnB[KCB * EDIM];    // bf16 copy
static __device__ float g_psum[8][NPOS];
static __device__ float g_invk[NPOS], g_invg[NPOS];
static __device__ float g_akd[NPOS],  g_agan[NPOS];
static __device__ float g_bkd[KCB],   g_bgan[KCB];
static __device__ float g_D[(size_t)NPOS * KCB];       // approx dsum, [n][k]
static __device__ unsigned g_keyu[NPOS];
static __device__ float g_Spt[2][64];
static __device__ int   g_idx[NPOS];

// ---------------- helpers ----------------
__device__ __forceinline__ float wsum(float s) {
#pragma unroll
    for (int o = 16; o > 0; o >>= 1) s += __shfl_xor_sync(0xffffffffu, s, o);
    return s;
}
__device__ __forceinline__ unsigned s2u(const void* p) {
    unsigned a;
    asm("{ .reg .u64 t; cvta.to.shared.u64 t, %1; cvt.u32.u64 %0, t; }" : "=r"(a) : "l"(p));
    return a;
}
__device__ __forceinline__ void cpasync16(unsigned s, const void* g) {
    asm volatile("cp.async.cg.shared.global [%0], [%1], 16;\n" :: "r"(s), "l"(g));
}
__device__ __forceinline__ void ldsm4(unsigned addr, unsigned &r0, unsigned &r1,
                                      unsigned &r2, unsigned &r3) {
    asm volatile("ldmatrix.sync.aligned.m8n8.x4.shared.b16 {%0,%1,%2,%3}, [%4];"
                 : "=r"(r0), "=r"(r1), "=r"(r2), "=r"(r3) : "r"(addr));
}
__device__ __forceinline__ void mma_bf16(float* c, unsigned a0, unsigned a1, unsigned a2,
                                         unsigned a3, unsigned b0, unsigned b1) {
    asm volatile("mma.sync.aligned.m16n8k16.row.col.f32.bf16.bf16.f32 "
                 "{%0,%1,%2,%3}, {%4,%5,%6,%7}, {%8,%9}, {%0,%1,%2,%3};"
                 : "+f"(c[0]), "+f"(c[1]), "+f"(c[2]), "+f"(c[3])
                 : "r"(a0), "r"(a1), "r"(a2), "r"(a3), "r"(b0), "r"(b1));
}

// ---------------- 1. normalize embeddings ----------------
__global__ void k_emb(const float* __restrict__ ekd, const float* __restrict__ egan) {
    int w = threadIdx.x >> 5, lane = threadIdx.x & 31;
    int k = blockIdx.x * 8 + w;
#pragma unroll
    for (int h = 0; h < 2; ++h) {
        const float* p = (h ? egan : ekd) + (size_t)k * SEMD;
        float v[8]; float s = 0.f;
#pragma unroll
        for (int j = 0; j < 8; ++j) { v[j] = p[lane + j * 32]; s += v[j] * v[j]; }
        s = wsum(s);
        float inv = 1.f / fmaxf(sqrtf(s), 1e-12f);
        float t = 0.f;
#pragma unroll
        for (int j = 0; j < 8; ++j) {
            float nv = v[j] * inv;
            size_t o = (size_t)k * EDIM + h * SEMD + lane + j * 32;
            g_En[o] = nv;
            g_EnB[o] = __float2bfloat16_rn(nv);
            t += nv * nv;
        }
        t = wsum(t);
        if (lane == 0) { if (h) g_bgan[k] = t; else g_bkd[k] = t; }
    }
}

// ---------------- 2. z sumsq partials ----------------
__global__ void k_zsumsq(const float* __restrict__ z) {
    int l = blockIdx.x * 256 + threadIdx.x, b = blockIdx.y, seg = blockIdx.z;
    const float* p = z + (size_t)b * D_ * L_ + (size_t)seg * 64 * L_ + l;
    float s = 0.f;
#pragma unroll 8
    for (int d = 0; d < 64; ++d) { float v = p[(size_t)d * L_]; s += v * v; }
    g_psum[seg][b * L_ + l] = s;
}

// ---------------- 3. finalize norms + init key/S ----------------
__global__ void k_zfinal() {
    int n = blockIdx.x * 256 + threadIdx.x;
    float s = g_psum[0][n] + g_psum[1][n] + g_psum[2][n] + g_psum[3][n];
    float inv = 1.f / fmaxf(sqrtf(s), 1e-12f);
    g_invk[n] = inv; g_akd[n] = s * inv * inv;
    float s2 = g_psum[4][n] + g_psum[5][n] + g_psum[6][n] + g_psum[7][n];
    float inv2 = 1.f / fmaxf(sqrtf(s2), 1e-12f);
    g_invg[n] = inv2; g_agan[n] = s2 * inv2 * inv2;
    g_keyu[n] = 0xFFFFFFFFu;
    if (n < 128) g_Spt[n >> 6][n & 63] = 0.f;
}

// ---------------- 4. transpose + normalize z into (n, e) ----------------
__global__ void k_ztrans(const float* __restrict__ z) {
    __shared__ float s[32][33];
    int d0 = blockIdx.x * 32, l0 = blockIdx.y * 32, b = blockIdx.z;
    int tx = threadIdx.x, ty = threadIdx.y;
#pragma unroll
    for (int q = 0; q < 4; ++q) {
        int dy = ty * 4 + q;
        s[dy][tx] = z[((size_t)b * D_ + d0 + dy) * L_ + l0 + tx];
    }
    __syncthreads();
    bool kdh = (d0 < SEMD);
#pragma unroll
    for (int q = 0; q < 4; ++q) {
        int lr = ty * 4 + q;
        int n = b * L_ + l0 + lr;
        float inv = kdh ? g_invk[n] : g_invg[n];
        float v = s[tx][lr] * inv;
        size_t o = (size_t)n * EDIM + d0 + tx;
        g_Zn[o] = v;
        g_ZnB[o] = __float2bfloat16_rn(v);
    }
}

// ---------------- 5. bf16 mma.sync GEMM + d + argmin + S ----------------
// CTA: 128 queries x 64 codes; 8 warps (4 m x 2 n), warp tile 32x32; k-chunk 32.
__global__ void __launch_bounds__(256, 2) k_gemm_mma() {
    __shared__ __nv_bfloat16 sA[2][128 * 40];   // 80B row stride -> conflict-free ldmatrix
    __shared__ __nv_bfloat16 sB[2][64 * 40];
    __shared__ float sRed[2][8];

    const int tid = threadIdx.x, lane = tid & 31, w = tid >> 5;
    const int kt = blockIdx.x, rt = blockIdx.y;
    const int row0 = rt * 128, k0 = kt * 64;
    const int wm = w & 3, wn = w >> 2;

    unsigned sAu = s2u(&sA[0][0]);
    unsigned sBu = s2u(&sB[0][0]);

    auto load_chunk = [&](int c, int b) {
        int e0 = c * 32;
        const __nv_bfloat16* Ag = g_ZnB + (size_t)row0 * EDIM + e0;
        const __nv_bfloat16* Bg = g_EnB + (size_t)k0 * EDIM + e0;
        unsigned ab = sAu + b * (128 * 80);
        unsigned bb = sBu + b * (64 * 80);
#pragma unroll
        for (int r2 = 0; r2 < 2; ++r2) {
            int q = tid + r2 * 256; int r = q >> 2, ch = q & 3;
            cpasync16(ab + r * 80 + ch * 16, Ag + (size_t)r * EDIM + ch * 8);
        }
        { int r = tid >> 2, ch = tid & 3;
          cpasync16(bb + r * 80 + ch * 16, Bg + (size_t)r * EDIM + ch * 8); }
        asm volatile("cp.async.commit_group;" ::: "memory");
    };

    float acck[2][4][4], accg[2][4][4];
#pragma unroll
    for (int t = 0; t < 2; ++t)
#pragma unroll
        for (int j = 0; j < 4; ++j)
#pragma unroll
            for (int q = 0; q < 4; ++q) { acck[t][j][q] = 0.f; accg[t][j][q] = 0.f; }

    const int lr = lane & 7, lg = lane >> 3;

    auto compute = [&](int b, float (&acc)[2][4][4]) {
        unsigned abase = sAu + b * (128 * 80);
        unsigned bbase = sBu + b * (64 * 80);
#pragma unroll
        for (int s = 0; s < 2; ++s) {
            unsigned a0[2], a1[2], a2[2], a3[2];
#pragma unroll
            for (int t = 0; t < 2; ++t) {
                int row = wm * 32 + t * 16 + lr + 8 * (lg & 1);
                int col = s * 16 + 8 * (lg >> 1);
                ldsm4(abase + row * 80 + col * 2, a0[t], a1[t], a2[t], a3[t]);
            }
            unsigned bf[4][2];
#pragma unroll
            for (int jp = 0; jp < 2; ++jp) {
                int brow = wn * 32 + (jp * 2 + (lg >> 1)) * 8 + lr;
                int bcol = s * 16 + 8 * (lg & 1);
                ldsm4(bbase + brow * 80 + bcol * 2,
                      bf[jp * 2][0], bf[jp * 2][1], bf[jp * 2 + 1][0], bf[jp * 2 + 1][1]);
            }
#pragma unroll
            for (int t = 0; t < 2; ++t)
#pragma unroll
                for (int j = 0; j < 4; ++j)
                    mma_bf16(acc[t][j], a0[t], a1[t], a2[t], a3[t], bf[j][0], bf[j][1]);
        }
    };

    load_chunk(0, 0);
    load_chunk(1, 1);
#pragma unroll 1
    for (int c = 0; c < 16; ++c) {
        if (c < 15) asm volatile("cp.async.wait_group 1;" ::: "memory");
        else        asm volatile("cp.async.wait_group 0;" ::: "memory");
        __syncthreads();
        if (c < 8) compute(c & 1, acck);
        else       compute(c & 1, accg);
        __syncthreads();
        if (c + 2 < 16) load_chunk(c + 2, c & 1);
    }

    // ---- epilogue ----
    const int lq = lane >> 2, lp = lane & 3;
    const int kb = k0 + wn * 32 + lp * 2;
    float bk[4][2], bg[4][2];
#pragma unroll
    for (int j = 0; j < 4; ++j) {
        bk[j][0] = g_bkd[kb + j * 8];  bk[j][1] = g_bkd[kb + j * 8 + 1];
        bg[j][0] = g_bgan[kb + j * 8]; bg[j][1] = g_bgan[kb + j * 8 + 1];
    }
    float Sk = 0.f, Sg = 0.f;
#pragma unroll
    for (int t = 0; t < 2; ++t) {
        int rA = row0 + wm * 32 + t * 16 + lq;
#pragma unroll
        for (int h = 0; h < 2; ++h) {
            int rr = rA + 8 * h;
            float ak_ = g_akd[rr], ag_ = g_agan[rr];
            unsigned rmin = 0xFFFFFFFFu;
#pragma unroll
            for (int j = 0; j < 4; ++j) {
                float ck0 = acck[t][j][2 * h], ck1 = acck[t][j][2 * h + 1];
                float cg0 = accg[t][j][2 * h], cg1 = accg[t][j][2 * h + 1];
                float dk0 = (ak_ + bk[j][0]) - 2.f * ck0;
                float dg0 = (ag_ + bg[j][0]) - 2.f * cg0;
                float dk1 = (ak_ + bk[j][1]) - 2.f * ck1;
                float dg1 = (ag_ + bg[j][1]) - 2.f * cg1;
                Sk = fmaf(dk0, dk0, Sk); Sk = fmaf(dk1, dk1, Sk);
                Sg = fmaf(dg0, dg0, Sg); Sg = fmaf(dg1, dg1, Sg);
                float d0 = dk0 + dg0, d1 = dk1 + dg1;
                rmin = min(rmin, min(__float_as_uint(d0), __float_as_uint(d1)));
                *(float2*)(g_D + (size_t)rr * KCB + kb + j * 8) = make_float2(d0, d1);
            }
            rmin = min(rmin, __shfl_xor_sync(0xffffffffu, rmin, 1));
            rmin = min(rmin, __shfl_xor_sync(0xffffffffu, rmin, 2));
            if (lp == 0) atomicMin(&g_keyu[rr], rmin);
        }
    }
    Sk = wsum(Sk); Sg = wsum(Sg);
    if (lane == 0) { sRed[0][w] = Sk; sRed[1][w] = Sg; }
    __syncthreads();
    if (tid < 2) {
        float s = 0.f;
#pragma unroll
        for (int i = 0; i < 8; ++i) s += sRed[tid][i];
        atomicAdd(&g_Spt[tid][rt], s);
    }
}

// ---------------- 6. scan + exact rescore (warp per query) ----------------
__global__ void k_scan(float* __restrict__ out) {
    int w = threadIdx.x >> 5, lane = threadIdx.x & 31;
    int n = blockIdx.x * 8 + w;
    float th = __uint_as_float(g_keyu[n]) + 1.2e-2f;
    const float* row = g_D + (size_t)n * KCB;
    int cand[4]; int nc = 0;
#pragma unroll 8
    for (int i = 0; i < 256; ++i) {
        float dv = row[i * 32 + lane];
        if (dv <= th && nc < 4) cand[nc++] = i * 32 + lane;
    }
    ull bkey = ~0ull;
    float akd = g_akd[n], agn = g_agan[n];
    const float* zr = g_Zn + (size_t)n * EDIM;
    for (int c2 = 0; c2 < nc; ++c2) {
        int k = cand[c2];
        const float* er = g_En + (size_t)k * EDIM;
        float ck = 0.f, cg = 0.f;
        for (int e = 0; e < SEMD; e += 4) {
            float4 zv = *(const float4*)(zr + e);
            float4 ev = *(const float4*)(er + e);
            ck = fmaf(zv.x, ev.x, ck); ck = fmaf(zv.y, ev.y, ck);
            ck = fmaf(zv.z, ev.z, ck); ck = fmaf(zv.w, ev.w, ck);
        }
        for (int e = SEMD; e < EDIM; e += 4) {
            float4 zv = *(const float4*)(zr + e);
            float4 ev = *(const float4*)(er + e);
            cg = fmaf(zv.x, ev.x, cg); cg = fmaf(zv.y, ev.y, cg);
            cg = fmaf(zv.z, ev.z, cg); cg = fmaf(zv.w, ev.w, cg);
        }
        float d = ((akd + g_bkd[k]) - 2.f * ck) + ((agn + g_bgan[k]) - 2.f * cg);
        ull key = ((ull)__float_as_uint(d) << 32) | (unsigned)k;
        if (key < bkey) bkey = key;
    }
#pragma unroll
    for (int o = 16; o > 0; o >>= 1) {
        ull other = __shfl_xor_sync(0xffffffffu, bkey, o);
        if (other < bkey) bkey = other;
    }
    if (lane == 0) {
        int bi = (int)(unsigned)bkey;
        g_idx[n] = bi;
        out[NQ + 2 + n] = (float)bi;
    }
    if (blockIdx.x == 0 && threadIdx.x < 2) {
        float s = 0.f;
        for (int i = 0; i < 64; ++i) s += g_Spt[threadIdx.x][i];
        out[NQ + threadIdx.x] = s * (1.f / 8192.f);
    }
}

// ---------------- 7. z_q gather ----------------
__global__ void k_zq(float* __restrict__ out) {
    int row0 = blockIdx.x * 64;
    int b = row0 >> 10, l0 = row0 & 1023;
    int lq = threadIdx.x & 63, dg = threadIdx.x >> 6;
    int n = row0 + lq;
    int kidx = g_idx[n];
    const float* Erow = g_En + (size_t)kidx * EDIM;
    const float* Zrow = g_Zn + (size_t)n * EDIM;
#pragma unroll 4
    for (int dit = 0; dit < 128; ++dit) {
        int d = dg * 128 + dit;
        float ev = Erow[d];
        float zn = Zrow[d];
        out[((size_t)b * D_ + d) * L_ + l0 + lq] = zn + (ev - zn);
    }
}

extern "C" void kernel_launch(void* const* d_in, const int* in_sizes, int n_in,
                              void* d_out, int out_size) {
    (void)in_sizes; (void)n_in; (void)out_size;
    const float* z    = (const float*)d_in[0];
    const float* ekd  = (const float*)d_in[1];
    const float* egan = (const float*)d_in[2];
    float* out = (float*)d_out;

    k_emb<<<KCB / 8, 256>>>(ekd, egan);
    k_zsumsq<<<dim3(4, 8, 8), 256>>>(z);
    k_zfinal<<<NPOS / 256, 256>>>();
    k_ztrans<<<dim3(16, 32, 8), dim3(32, 8)>>>(z);
    k_gemm_mma<<<dim3(128, 64), 256>>>();
    k_scan<<<NPOS / 8, 256>>>(out);
    k_zq<<<128, 256>>>(out);
}